// round 7
// baseline (speedup 1.0000x reference)
#include <cuda_runtime.h>
#include <math.h>
#include <stdint.h>

// ---------------------------------------------------------------------------
// Model_25975962206896: 4-qubit VQC, B=524288.
// Z = s† (W† M W) s with s = v⊗v⊗v⊗v rank-1 ⇒ Z collapses to a 15-term
// trigonometric polynomial in (f0, f1).
// SINGLE fused kernel. Per-block prologue (shuffle-based, ~1us, concurrent
// across the one resident wave):
//   warp 3 : 24 RXZX gates + 6 iSWAP sincos into shared
//   warps 0-2: propagate the 5 popcount indicator vectors u_n; lane holds one
//              complex amplitude, bin = 2*warp + lane/16, 30 shuffle steps
//   threads 0-14: one coefficient pair each -> sA/sB
// Then all 128 threads stream 4 elements each.
// ---------------------------------------------------------------------------

__device__ __forceinline__ float2 cmulf(float2 a, float2 b) {
    return make_float2(a.x * b.x - a.y * b.y, a.x * b.y + a.y * b.x);
}
__device__ __forceinline__ float2 caddf(float2 a, float2 b) {
    return make_float2(a.x + b.x, a.y + b.y);
}

// ---------------------------------------------------------------------------
// Per-element evaluation, grouped by power p (shallow dependency tree).
// ---------------------------------------------------------------------------
__device__ __forceinline__ float eval_one(float f0, float f1,
                                          const float* __restrict__ A,
                                          const float* __restrict__ B) {
    float s, c, s1, c1;
    __sincosf(0.5f * f1, &s, &c);
    __sincosf(f0, &s1, &c1);

    float c2 = fmaf(2.0f * c1, c1, -1.0f);
    float s2 = 2.0f * s1 * c1;
    float c3 = fmaf(c2, c1, -s2 * s1);
    float s3 = fmaf(s2, c1, c2 * s1);
    float c4 = fmaf(c3, c1, -s3 * s1);
    float s4 = fmaf(s3, c1, c3 * s1);

    // w[p] = c^(8-p) * s^p via shallow product tree
    float cc = c * c, ss = s * s;
    float c4p = cc * cc, s4p = ss * ss;
    float c3p = cc * c, s3p = ss * s;
    float w0 = c4p * c4p;
    float w1 = (c4p * c3p) * s;
    float w2 = (c4p * cc) * ss;
    float w3 = (c4p * c) * s3p;
    float w4 = c4p * s4p;
    float w5 = c3p * (s4p * s);
    float w6 = cc * (s4p * ss);
    float w7 = c * (s4p * s3p);
    float w8 = s4p * s4p;

    // trig factors T_k = A_k cos(m f0) + B_k sin(m f0)
    float T1  = fmaf(A[1],  c1, B[1]  * s1);
    float T6  = fmaf(A[6],  c1, B[6]  * s1);
    float T10 = fmaf(A[10], c1, B[10] * s1);
    float T13 = fmaf(A[13], c1, B[13] * s1);
    float T2  = fmaf(A[2],  c2, B[2]  * s2);
    float T7  = fmaf(A[7],  c2, B[7]  * s2);
    float T11 = fmaf(A[11], c2, B[11] * s2);
    float T3  = fmaf(A[3],  c3, B[3]  * s3);
    float T8  = fmaf(A[8],  c3, B[8]  * s3);
    float T4  = fmaf(A[4],  c4, B[4]  * s4);

    // group by power p
    float G0 = A[0];
    float G1 = T1;
    float G2 = A[5] + T2;
    float G3 = T6 + T3;
    float G4 = A[9] + T7 + T4;
    float G5 = T10 + T8;
    float G6 = A[12] + T11;
    float G7 = T13;
    float G8 = A[14];

    // balanced accumulation
    float t0 = fmaf(w0, G0, w1 * G1);
    float t1 = fmaf(w2, G2, w3 * G3);
    float t2 = fmaf(w4, G4, w5 * G5);
    float t3 = fmaf(w6, G6, w7 * G7);
    float t4 = w8 * G8;
    return (t0 + t1) + (t2 + t3) + t4;
}

// ---------------------------------------------------------------------------
__global__ __launch_bounds__(128, 8) void fused_kernel(
    const float4* __restrict__ in, const float* __restrict__ wU,
    const float* __restrict__ wR, const float* __restrict__ scp,
    const float* __restrict__ bip, float4* __restrict__ out) {

    __shared__ float2 gates[6][4][2][2];
    __shared__ float  isc[6], iss[6];
    __shared__ float2 sS[16][5];
    __shared__ float  sA[15], sB[15];

    const int tid = threadIdx.x;

    // ---- phase A: gates (warp 3) ----
    if (tid >= 96 && tid < 120) {
        int t = tid - 96;
        int l = t / 4, qb = t % 4;
        float a = wR[l * 12 + qb * 3 + 0];
        float b = wR[l * 12 + qb * 3 + 1];
        float c = wR[l * 12 + qb * 3 + 2];
        float sa, ca, sb, cb, sc3, cc3;
        __sincosf(0.5f * a, &sa, &ca);
        __sincosf(0.5f * b, &sb, &cb);
        __sincosf(0.5f * c, &sc3, &cc3);
        // g = RX(a) * RZ(b) * RX(c)
        float2 m1_00 = make_float2(ca, 0.f), m1_01 = make_float2(0.f, -sa);
        float2 m1_10 = make_float2(0.f, -sa), m1_11 = make_float2(ca, 0.f);
        float2 e0 = make_float2(cb, -sb), e1 = make_float2(cb, sb);
        float2 m3_00 = make_float2(cc3, 0.f), m3_01 = make_float2(0.f, -sc3);
        float2 m3_10 = make_float2(0.f, -sc3), m3_11 = make_float2(cc3, 0.f);
        float2 m23_00 = cmulf(e0, m3_00), m23_01 = cmulf(e0, m3_01);
        float2 m23_10 = cmulf(e1, m3_10), m23_11 = cmulf(e1, m3_11);
        gates[l][qb][0][0] = caddf(cmulf(m1_00, m23_00), cmulf(m1_01, m23_10));
        gates[l][qb][0][1] = caddf(cmulf(m1_00, m23_01), cmulf(m1_01, m23_11));
        gates[l][qb][1][0] = caddf(cmulf(m1_10, m23_00), cmulf(m1_11, m23_10));
        gates[l][qb][1][1] = caddf(cmulf(m1_10, m23_01), cmulf(m1_11, m23_11));
    } else if (tid >= 120 && tid < 126) {
        int l = tid - 120;
        float s, c;
        __sincosf(wU[l], &s, &c);
        isc[l] = c;
        iss[l] = s;
    }
    __syncthreads();

    // ---- phase B: propagate u_n via shuffles (warps 0..2) ----
    if (tid < 96) {
        const int lane = tid & 31;
        const int bin = 2 * (tid >> 5) + (lane >> 4);  // 0..5 (5 unused)
        const int r = lane & 15;
        float2 z = make_float2((__popc(r) == bin) ? 1.f : 0.f, 0.f);

        const int PAIRS[12] = {1, 2, 1, 3, 1, 2, 1, 3, 0, 3, 0, 2};
#pragma unroll
        for (int l = 0; l < 6; l++) {
            {   // iSWAP(theta) on (p,q)
                int mp = 8 >> PAIRS[2 * l], mq = 8 >> PAIRS[2 * l + 1];
                float c = isc[l], s = iss[l];
                float ox = __shfl_xor_sync(0xFFFFFFFFu, z.x, mp | mq);
                float oy = __shfl_xor_sync(0xFFFFFFFFu, z.y, mp | mq);
                bool act = ((r & mp) != 0) != ((r & mq) != 0);
                if (act)
                    z = make_float2(fmaf(c, z.x, -s * oy), fmaf(c, z.y, s * ox));
            }
#pragma unroll
            for (int qb = 0; qb < 4; qb++) {
                int mask = 8 >> qb;
                float ox = __shfl_xor_sync(0xFFFFFFFFu, z.x, mask);
                float oy = __shfl_xor_sync(0xFFFFFFFFu, z.y, mask);
                bool hi = (r & mask) != 0;
                float2 ga = hi ? gates[l][qb][1][1] : gates[l][qb][0][0];
                float2 gb = hi ? gates[l][qb][1][0] : gates[l][qb][0][1];
                float2 nz;
                nz.x = ga.x * z.x - ga.y * z.y + gb.x * ox - gb.y * oy;
                nz.y = ga.x * z.y + ga.y * z.x + gb.x * oy + gb.y * ox;
                z = nz;
            }
        }
        if (bin < 5) sS[r][bin] = z;
    }
    __syncthreads();

    // ---- phase C: coefficient pairs ----
    if (tid < 15) {
        const int NA[15] = {0, 0, 0, 0, 0, 1, 1, 1, 1, 2, 2, 2, 3, 3, 4};
        const int NB[15] = {0, 1, 2, 3, 4, 1, 2, 3, 4, 2, 3, 4, 3, 4, 4};
        int na = NA[tid], nb = NB[tid];
        float gx = 0.f, gy = 0.f;
#pragma unroll
        for (int i = 0; i < 16; i++) {
            float m = (i < 8) ? 1.f : -1.f;   // qubit 0 = bit 3
            float2 a = sS[i][na], b = sS[i][nb];
            gx += m * (a.x * b.x + a.y * b.y);
            gy += m * (a.x * b.y - a.y * b.x);
        }
        if (na == nb) { sA[tid] = gx;       sB[tid] = 0.f; }
        else          { sA[tid] = 2.f * gx; sB[tid] = -2.f * gy; }
    }
    __syncthreads();

    // ---- eval: 4 elements per thread ----
    float A[15], B[15];
#pragma unroll
    for (int k = 0; k < 15; k++) { A[k] = sA[k]; B[k] = sB[k]; }
    const float scale = __ldg(scp);
    const float bias  = __ldg(bip);
    const float K = 0.011180339887f;  // sqrt(2/1000)/4

    int t = blockIdx.x * blockDim.x + tid;
    float4 v0 = in[2 * t];
    float4 v1 = in[2 * t + 1];

    float Z0 = eval_one(v0.x, v0.y, A, B);
    float Z1 = eval_one(v0.z, v0.w, A, B);
    float Z2 = eval_one(v1.x, v1.y, A, B);
    float Z3 = eval_one(v1.z, v1.w, A, B);

    float4 r;
    r.x = fmaf(scale, fmaf(K, fmaf(Z0, Z0, -1.0f), Z0), bias);
    r.y = fmaf(scale, fmaf(K, fmaf(Z1, Z1, -1.0f), Z1), bias);
    r.z = fmaf(scale, fmaf(K, fmaf(Z2, Z2, -1.0f), Z2), bias);
    r.w = fmaf(scale, fmaf(K, fmaf(Z3, Z3, -1.0f), Z3), bias);
    out[t] = r;
}

// ---------------------------------------------------------------------------
extern "C" void kernel_launch(void* const* d_in, const int* in_sizes, int n_in,
                              void* d_out, int out_size) {
    const float* inputs = (const float*)d_in[0];  // [B,2] float32
    const float* wU     = (const float*)d_in[1];  // [6]
    const float* wR     = (const float*)d_in[2];  // [6,4,3]
    const float* sc     = (const float*)d_in[3];  // [] out_scale
    const float* bi     = (const float*)d_in[4];  // [] out_bias

    int nthreads = out_size / 4;  // 4 elements per thread
    int blocks = (nthreads + 127) / 128;
    fused_kernel<<<blocks, 128>>>((const float4*)inputs, wU, wR, sc, bi,
                                  (float4*)d_out);
}

// round 8
// speedup vs baseline: 1.1329x; 1.1329x over previous
#include <cuda_runtime.h>
#include <math.h>
#include <stdint.h>

// ---------------------------------------------------------------------------
// Model_25975962206896: 4-qubit VQC, B=524288.
// Z = s† (W† M W) s with s = v⊗v⊗v⊗v rank-1 ⇒ Z collapses to a 15-term
// trigonometric polynomial in (f0, f1).
//   setup_kernel: 1 block / 192 threads, shuffle-propagated popcount bins.
//   eval_kernel : 4 elements/thread, launched with PDL so it overlaps
//                 setup; cudaGridDependencySynchronize() before using coeffs.
// ---------------------------------------------------------------------------

__device__ float g_cA[15];
__device__ float g_cB[15];

__device__ __forceinline__ float2 cmulf(float2 a, float2 b) {
    return make_float2(a.x * b.x - a.y * b.y, a.x * b.y + a.y * b.x);
}
__device__ __forceinline__ float2 caddf(float2 a, float2 b) {
    return make_float2(a.x + b.x, a.y + b.y);
}

// ---------------------------------------------------------------------------
// Setup kernel: 1 block, 192 threads (proven R6 version).
// ---------------------------------------------------------------------------
__global__ void setup_kernel(const float* __restrict__ wU,
                             const float* __restrict__ wR) {
    __shared__ float2 gates[6][4][2][2];
    __shared__ float  isc[6], iss[6];
    __shared__ float2 sS[16][5];

    const int tid = threadIdx.x;

    if (tid >= 160 && tid < 184) {
        int t = tid - 160;
        int l = t / 4, qb = t % 4;
        float a = wR[l * 12 + qb * 3 + 0];
        float b = wR[l * 12 + qb * 3 + 1];
        float c = wR[l * 12 + qb * 3 + 2];
        float sa, ca, sb, cb, sc3, cc3;
        __sincosf(0.5f * a, &sa, &ca);
        __sincosf(0.5f * b, &sb, &cb);
        __sincosf(0.5f * c, &sc3, &cc3);
        // g = RX(a) * RZ(b) * RX(c)
        float2 m1_00 = make_float2(ca, 0.f), m1_01 = make_float2(0.f, -sa);
        float2 m1_10 = make_float2(0.f, -sa), m1_11 = make_float2(ca, 0.f);
        float2 e0 = make_float2(cb, -sb), e1 = make_float2(cb, sb);
        float2 m3_00 = make_float2(cc3, 0.f), m3_01 = make_float2(0.f, -sc3);
        float2 m3_10 = make_float2(0.f, -sc3), m3_11 = make_float2(cc3, 0.f);
        float2 m23_00 = cmulf(e0, m3_00), m23_01 = cmulf(e0, m3_01);
        float2 m23_10 = cmulf(e1, m3_10), m23_11 = cmulf(e1, m3_11);
        gates[l][qb][0][0] = caddf(cmulf(m1_00, m23_00), cmulf(m1_01, m23_10));
        gates[l][qb][0][1] = caddf(cmulf(m1_00, m23_01), cmulf(m1_01, m23_11));
        gates[l][qb][1][0] = caddf(cmulf(m1_10, m23_00), cmulf(m1_11, m23_10));
        gates[l][qb][1][1] = caddf(cmulf(m1_10, m23_01), cmulf(m1_11, m23_11));
    } else if (tid >= 184 && tid < 190) {
        int l = tid - 184;
        float s, c;
        __sincosf(wU[l], &s, &c);
        isc[l] = c;
        iss[l] = s;
    }
    __syncthreads();

    if (tid < 160) {
        const int n = tid >> 5;
        const int lane = tid & 31;
        const int r = lane & 15;
        float2 z = make_float2((__popc(r) == n) ? 1.f : 0.f, 0.f);

        const int PAIRS[12] = {1, 2, 1, 3, 1, 2, 1, 3, 0, 3, 0, 2};
#pragma unroll
        for (int l = 0; l < 6; l++) {
            {
                int mp = 8 >> PAIRS[2 * l], mq = 8 >> PAIRS[2 * l + 1];
                float c = isc[l], s = iss[l];
                float ox = __shfl_xor_sync(0xFFFFFFFFu, z.x, mp | mq);
                float oy = __shfl_xor_sync(0xFFFFFFFFu, z.y, mp | mq);
                bool act = ((r & mp) != 0) != ((r & mq) != 0);
                if (act)
                    z = make_float2(fmaf(c, z.x, -s * oy), fmaf(c, z.y, s * ox));
            }
#pragma unroll
            for (int qb = 0; qb < 4; qb++) {
                int mask = 8 >> qb;
                float ox = __shfl_xor_sync(0xFFFFFFFFu, z.x, mask);
                float oy = __shfl_xor_sync(0xFFFFFFFFu, z.y, mask);
                bool hi = (r & mask) != 0;
                float2 ga = hi ? gates[l][qb][1][1] : gates[l][qb][0][0];
                float2 gb = hi ? gates[l][qb][1][0] : gates[l][qb][0][1];
                float2 nz;
                nz.x = ga.x * z.x - ga.y * z.y + gb.x * ox - gb.y * oy;
                nz.y = ga.x * z.y + ga.y * z.x + gb.x * oy + gb.y * ox;
                z = nz;
            }
        }
        if (lane < 16) sS[r][n] = z;
    }
    __syncthreads();

    if (tid < 15) {
        const int NA[15] = {0, 0, 0, 0, 0, 1, 1, 1, 1, 2, 2, 2, 3, 3, 4};
        const int NB[15] = {0, 1, 2, 3, 4, 1, 2, 3, 4, 2, 3, 4, 3, 4, 4};
        int na = NA[tid], nb = NB[tid];
        float gx = 0.f, gy = 0.f;
#pragma unroll
        for (int i = 0; i < 16; i++) {
            float m = (i < 8) ? 1.f : -1.f;   // qubit 0 = bit 3
            float2 a = sS[i][na], b = sS[i][nb];
            gx += m * (a.x * b.x + a.y * b.y);
            gy += m * (a.x * b.y - a.y * b.x);
        }
        if (na == nb) { g_cA[tid] = gx;       g_cB[tid] = 0.f; }
        else          { g_cA[tid] = 2.f * gx; g_cB[tid] = -2.f * gy; }
    }
}

// ---------------------------------------------------------------------------
// Per-element evaluation, grouped by power p (shallow dependency tree).
// ---------------------------------------------------------------------------
__device__ __forceinline__ float eval_one(float f0, float f1,
                                          const float* __restrict__ A,
                                          const float* __restrict__ B) {
    float s, c, s1, c1;
    __sincosf(0.5f * f1, &s, &c);
    __sincosf(f0, &s1, &c1);

    float c2 = fmaf(2.0f * c1, c1, -1.0f);
    float s2 = 2.0f * s1 * c1;
    float c3 = fmaf(c2, c1, -s2 * s1);
    float s3 = fmaf(s2, c1, c2 * s1);
    float c4 = fmaf(c3, c1, -s3 * s1);
    float s4 = fmaf(s3, c1, c3 * s1);

    float cc = c * c, ss = s * s;
    float c4p = cc * cc, s4p = ss * ss;
    float c3p = cc * c, s3p = ss * s;
    float w0 = c4p * c4p;
    float w1 = (c4p * c3p) * s;
    float w2 = (c4p * cc) * ss;
    float w3 = (c4p * c) * s3p;
    float w4 = c4p * s4p;
    float w5 = c3p * (s4p * s);
    float w6 = cc * (s4p * ss);
    float w7 = c * (s4p * s3p);
    float w8 = s4p * s4p;

    float T1  = fmaf(A[1],  c1, B[1]  * s1);
    float T6  = fmaf(A[6],  c1, B[6]  * s1);
    float T10 = fmaf(A[10], c1, B[10] * s1);
    float T13 = fmaf(A[13], c1, B[13] * s1);
    float T2  = fmaf(A[2],  c2, B[2]  * s2);
    float T7  = fmaf(A[7],  c2, B[7]  * s2);
    float T11 = fmaf(A[11], c2, B[11] * s2);
    float T3  = fmaf(A[3],  c3, B[3]  * s3);
    float T8  = fmaf(A[8],  c3, B[8]  * s3);
    float T4  = fmaf(A[4],  c4, B[4]  * s4);

    float G0 = A[0];
    float G1 = T1;
    float G2 = A[5] + T2;
    float G3 = T6 + T3;
    float G4 = A[9] + T7 + T4;
    float G5 = T10 + T8;
    float G6 = A[12] + T11;
    float G7 = T13;
    float G8 = A[14];

    float t0 = fmaf(w0, G0, w1 * G1);
    float t1 = fmaf(w2, G2, w3 * G3);
    float t2 = fmaf(w4, G4, w5 * G5);
    float t3 = fmaf(w6, G6, w7 * G7);
    float t4 = w8 * G8;
    return (t0 + t1) + (t2 + t3) + t4;
}

// ---------------------------------------------------------------------------
// Eval kernel: 4 elements/thread. PDL: loads issue first, then grid-dep sync
// before reading the coefficients written by setup_kernel.
// ---------------------------------------------------------------------------
__global__ __launch_bounds__(128) void eval_kernel(
    const float4* __restrict__ in, const float* __restrict__ scp,
    const float* __restrict__ bip, float4* __restrict__ out) {

    int t = blockIdx.x * blockDim.x + threadIdx.x;
    // Issue the batch loads before waiting on the setup kernel: DRAM latency
    // overlaps the programmatic dependency wait.
    float4 v0 = in[2 * t];
    float4 v1 = in[2 * t + 1];

#if __CUDA_ARCH__ >= 900
    cudaGridDependencySynchronize();
#endif

    float A[15], B[15];
#pragma unroll
    for (int k = 0; k < 15; k++) {
        A[k] = __ldg(&g_cA[k]);
        B[k] = __ldg(&g_cB[k]);
    }
    const float scale = __ldg(scp);
    const float bias  = __ldg(bip);
    const float K = 0.011180339887f;  // sqrt(2/1000)/4

    float Z0 = eval_one(v0.x, v0.y, A, B);
    float Z1 = eval_one(v0.z, v0.w, A, B);
    float Z2 = eval_one(v1.x, v1.y, A, B);
    float Z3 = eval_one(v1.z, v1.w, A, B);

    float4 r;
    r.x = fmaf(scale, fmaf(K, fmaf(Z0, Z0, -1.0f), Z0), bias);
    r.y = fmaf(scale, fmaf(K, fmaf(Z1, Z1, -1.0f), Z1), bias);
    r.z = fmaf(scale, fmaf(K, fmaf(Z2, Z2, -1.0f), Z2), bias);
    r.w = fmaf(scale, fmaf(K, fmaf(Z3, Z3, -1.0f), Z3), bias);
    out[t] = r;
}

// ---------------------------------------------------------------------------
extern "C" void kernel_launch(void* const* d_in, const int* in_sizes, int n_in,
                              void* d_out, int out_size) {
    const float* inputs = (const float*)d_in[0];  // [B,2] float32
    const float* wU     = (const float*)d_in[1];  // [6]
    const float* wR     = (const float*)d_in[2];  // [6,4,3]
    const float* sc     = (const float*)d_in[3];  // [] out_scale
    const float* bi     = (const float*)d_in[4];  // [] out_bias

    setup_kernel<<<1, 192>>>(wU, wR);

    int nthreads = out_size / 4;  // 4 elements per thread
    int blocks = (nthreads + 127) / 128;

    // Programmatic dependent launch: eval dispatches concurrently with setup;
    // the grid-dependency sync inside orders the coefficient reads.
    cudaLaunchConfig_t cfg = {};
    cfg.gridDim = dim3((unsigned)blocks);
    cfg.blockDim = dim3(128);
    cfg.dynamicSmemBytes = 0;
    cfg.stream = 0;
    cudaLaunchAttribute attr[1];
    attr[0].id = cudaLaunchAttributeProgrammaticStreamSerialization;
    attr[0].val.programmaticStreamSerializationAllowed = 1;
    cfg.attrs = attr;
    cfg.numAttrs = 1;
    cudaError_t err = cudaLaunchKernelEx(&cfg, eval_kernel,
                                         (const float4*)inputs, sc, bi,
                                         (float4*)d_out);
    if (err != cudaSuccess) {
        // Fallback: plain launch (still correct, just serialized).
        eval_kernel<<<blocks, 128>>>((const float4*)inputs, sc, bi,
                                     (float4*)d_out);
    }
}